// round 11
// baseline (speedup 1.0000x reference)
#include <cuda_runtime.h>
#include <cuda_bf16.h>

// CGA motor sandwich out = grade1(M * P * ~M)[:, :6], Cl(7,1), B=1024.
// Compile-time byte tables index a SIGNED-DUPLICATE motor array sm2[256]
// (sm2[j]=m[j], sm2[j+128]=-m[j], slot 127=0): table byte -> LDS -> FMA,
// no sign ops at runtime.
//
// Block = 1024 threads (32 warps), EIGHT batches per block (grid = 128):
//   head:    bat=t>>7 (0..7), j=t&127: motor LDG + signed-dup STS;
//            point in registers (3x LDG.64); t1 word prefetched. All threads busy.
//   stage 1: bin j of mx for batch bat (8 LDS + 8 FMA), all 1024 threads.
//   stage 2: 48 tasks (8 batches x 6 outputs) over 32 warps; every warp does
//            task w, warps 0..15 also do task 32+w. Each task: 127-term dot,
//            4 LDS-pairs + 4 FMA + one 5-level shfl chain; lane 0 stores.

#define NM 127

struct Tables {
    unsigned t1[128 * 2];  // bin byte j: sm2 index (a | neg<<7), pairs p[j]
    unsigned t2[6 * 32];   // [k][lane] byte i: sm2 index for bin i*32+lane
};

__host__ __device__ constexpr int popc8(int m) {
    int c = 0;
    for (int i = 0; i < 8; i++) c += (m >> i) & 1;
    return c;
}

__host__ __device__ constexpr int sign_of(int a, int b) {
    int s = 1;
    int aa = a >> 1;
    while (aa) { if (popc8(aa & b) & 1) s = -s; aa >>= 1; }
    if ((a & b) & 0x80) s = -s;   // metric: only basis vector 7 squares to -1
    return s;
}

__host__ __device__ constexpr Tables make_tables() {
    Tables T{};
    // masks sorted by (popcount, value) — reference ordering
    int masks[256] = {};
    int t = 0;
    for (int g = 0; g <= 8; ++g)
        for (int m = 0; m < 256; ++m)
            if (popc8(m) == g) masks[t++] = m;

    int mmrank[256] = {};  int nm = 0;
    int oddmask[128] = {}; int nodd = 0;
    for (int i = 0; i < 256; ++i) {
        int m = masks[i], g = popc8(m);
        if ((g & 1) == 0 && m != 255) { mmrank[m] = nm; ++nm; }
        if (g & 1)                    { oddmask[nodd] = m; ++nodd; }
    }

    // stage 1: bin bi, term j pairs p[j] with motor comp rank(mask ^ (1<<j))
    for (int bi = 0; bi < 128; ++bi) {
        int rm = oddmask[bi];
        unsigned w0 = 0, w1 = 0;
        for (int j = 0; j < 8; ++j) {
            int am = rm ^ (1 << j);
            unsigned byte = 127;                       // pseudoscalar -> sm2[127]==0
            if (am != 255) {
                int s = sign_of(am, 1 << j);
                byte = (unsigned)mmrank[am] | ((s < 0) ? 128u : 0u);
            }
            if (j < 4) w0 |= byte << (8 * j);
            else       w1 |= byte << (8 * (j - 4));
        }
        T.t1[bi * 2]     = w0;
        T.t1[bi * 2 + 1] = w1;
    }

    // stage 2: out blade 1<<k; bin im contributes with right operand jm = im^(1<<k)
    for (int k = 0; k < 6; ++k) {
        for (int lane = 0; lane < 32; ++lane) {
            unsigned word = 0;
            for (int i = 0; i < 4; ++i) {
                int bi = i * 32 + lane;
                int im = oddmask[bi];
                int jm = im ^ (1 << k);
                unsigned byte = 127;                   // pseudoscalar -> sm2[127]==0
                if (jm != 255) {
                    int g  = popc8(jm);
                    int rs = ((g * (g - 1) / 2) & 1) ? -1 : 1;  // reverse sign
                    int s  = sign_of(im, jm) * rs;
                    byte = (unsigned)mmrank[jm] | ((s < 0) ? 128u : 0u);
                }
                word |= byte << (8 * i);
            }
            T.t2[k * 32 + lane] = word;
        }
    }
    return T;
}

__device__ const Tables g_T = make_tables();

__global__ __launch_bounds__(1024)
void cga_sandwich_kernel(const float* __restrict__ motor,
                         const float* __restrict__ x,
                         float* __restrict__ out,
                         int Bn)
{
    __shared__ float sm2[8][256];   // signed-duplicate motors, 8 batches
    __shared__ float smx[8][128];   // stage-1 result (odd-grade bins)

    const int t  = threadIdx.x;
    const int b0 = blockIdx.x * 8;
    const int w  = t >> 5, lane = t & 31;

    // stage-2 task(s) for THIS warp — prefetch table words (no smem dep)
    const int tskA = w;                       // 0..31
    const int batA = tskA / 6, kA = tskA - batA * 6;
    const unsigned wdA = __ldg(&g_T.t2[kA * 32 + lane]);
    const int tskB = 32 + w;                  // valid if w < 16
    const int batB = tskB / 6, kB = tskB - batB * 6;
    const unsigned wdB = (w < 16) ? __ldg(&g_T.t2[kB * 32 + lane]) : 0u;

    const int bat = t >> 7;                   // head batch 0..7
    const int j   = t & 127;

    // motor load: 1 coalesced LDG per thread, signed-duplicate store
    const int bb = (b0 + bat < Bn) ? b0 + bat : Bn - 1;
    float v = (j < NM) ? __ldg(&motor[(size_t)bb * NM + j]) : 0.0f;
    sm2[bat][j]       = v;
    sm2[bat][j + 128] = -v;

    // stage-1 table word (prefetch; independent of smem)
    const uint2 wd1 = __ldg((const uint2*)(g_T.t1 + j * 2));

    // point for this thread's batch (registers), 3x LDG.64
    float p[8];
    {
        const float2* xr = (const float2*)(x + (size_t)bb * 6);
        float2 v01 = __ldg(xr), v23 = __ldg(xr + 1), v45 = __ldg(xr + 2);
        float h = 0.5f * (v01.x*v01.x + v01.y*v01.y + v23.x*v23.x +
                          v23.y*v23.y + v45.x*v45.x + v45.y*v45.y);
        p[0] = v01.x; p[1] = v01.y; p[2] = v23.x;
        p[3] = v23.y; p[4] = v45.x; p[5] = v45.y;
        p[6] = h - 0.5f; p[7] = h + 0.5f;
    }
    __syncthreads();

    // ---- stage 1: every thread computes bin j of mx for its batch ----
    {
        const float* s = sm2[bat];
        unsigned e;
        float a;
        e = wd1.x & 255u;         a = s[e] * p[0];
        e = (wd1.x >> 8) & 255u;  a = fmaf(s[e], p[1], a);
        e = (wd1.x >> 16) & 255u; a = fmaf(s[e], p[2], a);
        e = wd1.x >> 24;          a = fmaf(s[e], p[3], a);
        e = wd1.y & 255u;         a = fmaf(s[e], p[4], a);
        e = (wd1.y >> 8) & 255u;  a = fmaf(s[e], p[5], a);
        e = (wd1.y >> 16) & 255u; a = fmaf(s[e], p[6], a);
        e = wd1.y >> 24;          a = fmaf(s[e], p[7], a);
        smx[bat][j] = a;
    }
    __syncthreads();

    // ---- stage 2: task A (all warps) ----
    {
        const float* sb  = sm2[batA];
        const float* mxb = smx[batA];
        float acc;
        acc = mxb[lane]            * sb[wdA & 255u];
        acc = fmaf(mxb[32 + lane], sb[(wdA >> 8)  & 255u], acc);
        acc = fmaf(mxb[64 + lane], sb[(wdA >> 16) & 255u], acc);
        acc = fmaf(mxb[96 + lane], sb[wdA >> 24],          acc);
        #pragma unroll
        for (int off = 16; off; off >>= 1)
            acc += __shfl_xor_sync(0xffffffffu, acc, off);
        if (lane == 0 && b0 + batA < Bn)
            out[(size_t)(b0 + batA) * 6 + kA] = acc;
    }

    // ---- stage 2: task B (warps 0..15) ----
    if (w < 16) {
        const float* sb  = sm2[batB];
        const float* mxb = smx[batB];
        float acc;
        acc = mxb[lane]            * sb[wdB & 255u];
        acc = fmaf(mxb[32 + lane], sb[(wdB >> 8)  & 255u], acc);
        acc = fmaf(mxb[64 + lane], sb[(wdB >> 16) & 255u], acc);
        acc = fmaf(mxb[96 + lane], sb[wdB >> 24],          acc);
        #pragma unroll
        for (int off = 16; off; off >>= 1)
            acc += __shfl_xor_sync(0xffffffffu, acc, off);
        if (lane == 0 && b0 + batB < Bn)
            out[(size_t)(b0 + batB) * 6 + kB] = acc;
    }
}

extern "C" void kernel_launch(void* const* d_in, const int* in_sizes, int n_in,
                              void* d_out, int out_size)
{
    const float* motor = (const float*)d_in[0];   // [B, 127]
    const float* x     = (const float*)d_in[1];   // [B, 6]
    float* out = (float*)d_out;

    int Bn = in_sizes[0] / NM;                    // 1024
    int grid = (Bn + 7) / 8;                      // 8 batches per 1024-thread block
    cga_sandwich_kernel<<<grid, 1024>>>(motor, x, out, Bn);
}